// round 16
// baseline (speedup 1.0000x reference)
#include <cuda_runtime.h>
#include <cuda_fp16.h>
#include <cstdint>

#define B_DIM 2
#define T_DIM 4096
#define C_DIM 1024
#define H_DIM 16
#define D_DIM 64
#define MROWS (B_DIM * T_DIM)   // 8192
#define KDIM  C_DIM             // 1024

// ---------------- static device scratch (no allocs allowed) ----------------
__device__ __align__(256) __half g_x16[(size_t)MROWS * KDIM];
__device__ __align__(256) __half g_wq16[(size_t)3 * C_DIM * KDIM];
__device__ __align__(256) __half g_wo16[(size_t)C_DIM * KDIM];
__device__ __align__(256) __half g_att16[(size_t)MROWS * C_DIM];
// per-head [b,h,t,d] fp16 (q pre-scaled by 0.125*log2e)
__device__ __align__(256) __half g_q16[(size_t)MROWS * C_DIM];
__device__ __align__(256) __half g_k16[(size_t)MROWS * C_DIM];
__device__ __align__(256) __half g_v16[(size_t)MROWS * C_DIM];

// ---------------------------------------------------------------------------
// PTX helpers
// ---------------------------------------------------------------------------
__device__ __forceinline__ uint32_t cvta_s(const void* p) {
    uint32_t a;
    asm("{ .reg .u64 t; cvta.to.shared.u64 t, %1; cvt.u32.u64 %0, t; }"
        : "=r"(a) : "l"(p));
    return a;
}

__device__ __forceinline__ void cp16(uint32_t dst, const void* src) {
    asm volatile("cp.async.cg.shared.global [%0], [%1], 16;"
                 :: "r"(dst), "l"(src) : "memory");
}

__device__ __forceinline__ void ldm4(uint32_t addr, uint32_t& r0, uint32_t& r1,
                                     uint32_t& r2, uint32_t& r3) {
    asm volatile("ldmatrix.sync.aligned.m8n8.x4.shared.b16 {%0,%1,%2,%3}, [%4];"
                 : "=r"(r0), "=r"(r1), "=r"(r2), "=r"(r3) : "r"(addr));
}

__device__ __forceinline__ void ldm4t(uint32_t addr, uint32_t& r0, uint32_t& r1,
                                      uint32_t& r2, uint32_t& r3) {
    asm volatile("ldmatrix.sync.aligned.m8n8.x4.trans.shared.b16 {%0,%1,%2,%3}, [%4];"
                 : "=r"(r0), "=r"(r1), "=r"(r2), "=r"(r3) : "r"(addr));
}

__device__ __forceinline__ void mma_f16(float* d, const uint32_t* a,
                                        uint32_t b0, uint32_t b1) {
    asm volatile(
        "mma.sync.aligned.m16n8k16.row.col.f32.f16.f16.f32 "
        "{%0,%1,%2,%3}, {%4,%5,%6,%7}, {%8,%9}, {%0,%1,%2,%3};"
        : "+f"(d[0]), "+f"(d[1]), "+f"(d[2]), "+f"(d[3])
        : "r"(a[0]), "r"(a[1]), "r"(a[2]), "r"(a[3]), "r"(b0), "r"(b1));
}

__device__ __forceinline__ float ex2f(float x) {
    float y;
    asm("ex2.approx.f32 %0, %1;" : "=f"(y) : "f"(x));
    return y;
}

__device__ __forceinline__ uint32_t pack16(float lo, float hi) {
    uint32_t r;
    asm("cvt.rn.f16x2.f32 %0, %1, %2;" : "=r"(r) : "f"(hi), "f"(lo));
    return r;
}

// SW128: row r (128B rows), 16B chunk c(0..7) -> byte offset
__device__ __forceinline__ uint32_t swz(uint32_t r, uint32_t c) {
    return r * 128 + ((c ^ (r & 7)) << 4);
}

// ---------------------------------------------------------------------------
// fused convert fp32 -> fp16 for all three inputs in one launch
// ---------------------------------------------------------------------------
__global__ __launch_bounds__(256) void cvt_fp16_all(
    const float4* __restrict__ in0, uint32_t* __restrict__ out0, int n0,
    const float4* __restrict__ in1, uint32_t* __restrict__ out1, int n1,
    const float4* __restrict__ in2, uint32_t* __restrict__ out2, int n2)
{
    int i = blockIdx.x * blockDim.x + threadIdx.x;
    const float4* in;
    uint32_t* out;
    if (i < n0) {
        in = in0; out = out0;
    } else if (i < n0 + n1) {
        i -= n0; in = in1; out = out1;
    } else {
        i -= n0 + n1;
        if (i >= n2) return;
        in = in2; out = out2;
    }
    float4 v = in[i];
    out[2 * i]     = pack16(v.x, v.y);
    out[2 * i + 1] = pack16(v.z, v.w);
}

// ---------------------------------------------------------------------------
// fp16 GEMM (identical to R13 best): CTA 128x128, 4 warps, BK=64, 3-stage.
// MODE 0: write fp32 C.   MODE 1: write fp16 q(scaled)/k/v in [b,h,t,d].
// ---------------------------------------------------------------------------
#define GTILE   16384
#define GSTAGE  32768
#define GNSTAGE 3

__device__ __forceinline__ void g_ldtile(
    const __half* __restrict__ G, int K, int row0, int k0,
    uint32_t base, int tid)
{
#pragma unroll
    for (int t = 0; t < 8; t++) {
        int idx = tid + t * 128;
        int r = idx >> 3, c = idx & 7;
        cp16(base + swz(r, c), G + (size_t)(row0 + r) * K + k0 + c * 8);
    }
}

#define QSCALE 0.180336880f   // 0.125 * log2(e)

template <int MODE>
__global__ __launch_bounds__(128, 2) void gemm_f16(
    const __half* __restrict__ A, const __half* __restrict__ B,
    float* __restrict__ C,
    __half* __restrict__ q16, __half* __restrict__ k16,
    __half* __restrict__ v16, int N, int K)
{
    extern __shared__ __align__(128) char smraw[];
    const uint32_t smbase = cvta_s(smraw);

    const int tid  = threadIdx.x;
    const int wid  = tid >> 5;
    const int lane = tid & 31;
    const int n0 = blockIdx.x * 128;
    const int m0 = blockIdx.y * 128;
    const int wm = (wid & 1) * 64;
    const int wn = (wid >> 1) * 64;
    const int lr = lane & 15;
    const int lc = lane >> 4;

    float acc[4][8][4];
#pragma unroll
    for (int i = 0; i < 4; i++)
#pragma unroll
        for (int j = 0; j < 8; j++)
#pragma unroll
            for (int k = 0; k < 4; k++) acc[i][j][k] = 0.0f;

    const int nch = K / 64;

#pragma unroll
    for (int c = 0; c < 2; c++) {
        uint32_t sb = smbase + c * GSTAGE;
        g_ldtile(A, K, m0, c * 64, sb, tid);
        g_ldtile(B, K, n0, c * 64, sb + GTILE, tid);
        asm volatile("cp.async.commit_group;" ::: "memory");
    }

    for (int c = 0; c < nch; c++) {
        if (c + 1 < nch)
            asm volatile("cp.async.wait_group 1;" ::: "memory");
        else
            asm volatile("cp.async.wait_group 0;" ::: "memory");
        __syncthreads();

        if (c + 2 < nch) {
            uint32_t db = smbase + ((c + 2) % GNSTAGE) * GSTAGE;
            int kk = (c + 2) * 64;
            g_ldtile(A, K, m0, kk, db, tid);
            g_ldtile(B, K, n0, kk, db + GTILE, tid);
            asm volatile("cp.async.commit_group;" ::: "memory");
        }

        uint32_t sb = smbase + (c % GNSTAGE) * GSTAGE;

#pragma unroll
        for (int ks = 0; ks < 4; ks++) {
            const uint32_t ch = ks * 2 + lc;
            uint32_t af[4][4];
#pragma unroll
            for (int mt = 0; mt < 4; mt++) {
                uint32_t row = wm + mt * 16 + lr;
                ldm4(sb + row * 128 + ((ch ^ (row & 7)) << 4),
                     af[mt][0], af[mt][1], af[mt][2], af[mt][3]);
            }
            uint32_t bf[4][4];
#pragma unroll
            for (int p = 0; p < 4; p++) {
                uint32_t row = wn + p * 16 + lr;
                ldm4(sb + GTILE + row * 128 + ((ch ^ (row & 7)) << 4),
                     bf[p][0], bf[p][1], bf[p][2], bf[p][3]);
            }
#pragma unroll
            for (int mt = 0; mt < 4; mt++) {
#pragma unroll
                for (int nt = 0; nt < 8; nt++) {
                    const int p = nt >> 1, h = nt & 1;
                    mma_f16(acc[mt][nt], af[mt], bf[p][h], bf[p][2 + h]);
                }
            }
        }
    }

    const int er = lane >> 2;
    const int ec = (lane & 3) * 2;
#pragma unroll
    for (int mt = 0; mt < 4; mt++) {
#pragma unroll
        for (int nt = 0; nt < 8; nt++) {
            if (MODE == 0) {
                size_t row = (size_t)(m0 + wm + mt * 16 + er);
                int col = n0 + wn + nt * 8 + ec;
                *(float2*)(C + row * N + col) =
                    make_float2(acc[mt][nt][0], acc[mt][nt][1]);
                *(float2*)(C + (row + 8) * N + col) =
                    make_float2(acc[mt][nt][2], acc[mt][nt][3]);
            } else {
                int col = n0 + wn + nt * 8 + ec;
                int type = col >> 10;
                int hh = (col >> 6) & 15;
                int d = col & 63;
                __half* dst = (type == 0) ? q16 : (type == 1) ? k16 : v16;
                float sc = (type == 0) ? QSCALE : 1.0f;
#pragma unroll
                for (int rr = 0; rr < 2; rr++) {
                    int row = m0 + wm + mt * 16 + er + rr * 8;
                    int bb = row >> 12, tt = row & 4095;
                    size_t o = ((size_t)(bb * H_DIM + hh) * T_DIM + tt) * 64 + d;
                    *(uint32_t*)(dst + o) =
                        pack16(acc[mt][nt][2 * rr] * sc,
                               acc[mt][nt][2 * rr + 1] * sc);
                }
            }
        }
    }
}

// ---------------------------------------------------------------------------
// Flash attention, fp16, causal. Br=128 (4 warps x 32 rows), Bc=64,
// SW128 smem, 2-stage, 48KB, 3 CTAs/SM.
// Per-m-block processing (QK(mb)->SM(mb)->PV(mb)) keeps only one s[8][4]
// live; Q frags reloaded from the persistent Q smem tile -> ~145 live regs.
// ---------------------------------------------------------------------------
#define AQT 16384
#define AKT 8192
#define AST 16384
#define ASOFF 16384

__device__ __forceinline__ void kload(
    const __half* __restrict__ k16, const __half* __restrict__ v16,
    size_t gbase, uint32_t st, int tid)
{
#pragma unroll
    for (int t = 0; t < 8; t++) {
        int idx = tid + t * 128;
        int tile = idx >> 9;                // 0=K 1=V
        int rem = idx & 511;
        int r = rem >> 3, c = rem & 7;
        cp16(st + tile * AKT + swz(r, c),
             (tile ? v16 : k16) + gbase + (size_t)r * 64 + c * 8);
    }
}

// process one m-block for one k-tile: QK -> mask -> softmax -> PV
__device__ __forceinline__ void mb_tile(
    uint32_t st, uint32_t qrb, uint32_t qkey, int lr, int lc, int lane,
    int kt, int rowbase, bool need_mask,
    float& m0r, float& m1r, float& l0r, float& l1r, float (&o)[8][4])
{
    // ---- S = Q K^T for this m-block ----
    float s[8][4];
#pragma unroll
    for (int i = 0; i < 8; i++)
#pragma unroll
        for (int j = 0; j < 4; j++) s[i][j] = 0.0f;

#pragma unroll
    for (int ks = 0; ks < 4; ks++) {
        uint32_t ch = ks * 2 + lc;
        uint32_t qa[4];
        ldm4(qrb + ((ch ^ qkey) << 4), qa[0], qa[1], qa[2], qa[3]);
#pragma unroll
        for (int ng = 0; ng < 4; ng++) {
            uint32_t row = ng * 16 + lr;
            uint32_t h0, h1, h2, h3;
            ldm4(st + row * 128 + ((ch ^ (row & 7)) << 4), h0, h1, h2, h3);
            mma_f16(s[2 * ng],     qa, h0, h2);
            mma_f16(s[2 * ng + 1], qa, h1, h3);
        }
    }

    // ---- causal mask ----
    if (need_mask) {
        const int cb = kt * 64 + (lane & 3) * 2;
        const int rb0 = rowbase + (lane >> 2);
#pragma unroll
        for (int nt = 0; nt < 8; nt++) {
            int c0 = cb + nt * 8;
            if (c0     > rb0)     s[nt][0] = -1e30f;
            if (c0 + 1 > rb0)     s[nt][1] = -1e30f;
            if (c0     > rb0 + 8) s[nt][2] = -1e30f;
            if (c0 + 1 > rb0 + 8) s[nt][3] = -1e30f;
        }
    }

    // ---- online softmax (scores in log2 units) ----
    float mx0 = s[0][0], mx1 = s[0][2];
#pragma unroll
    for (int nt = 0; nt < 8; nt++) {
        mx0 = fmaxf(mx0, fmaxf(s[nt][0], s[nt][1]));
        mx1 = fmaxf(mx1, fmaxf(s[nt][2], s[nt][3]));
    }
    mx0 = fmaxf(mx0, __shfl_xor_sync(0xffffffffu, mx0, 1));
    mx0 = fmaxf(mx0, __shfl_xor_sync(0xffffffffu, mx0, 2));
    mx1 = fmaxf(mx1, __shfl_xor_sync(0xffffffffu, mx1, 1));
    mx1 = fmaxf(mx1, __shfl_xor_sync(0xffffffffu, mx1, 2));

    float mn0 = fmaxf(m0r, mx0), mn1 = fmaxf(m1r, mx1);
    float a0 = ex2f(m0r - mn0);
    float a1 = ex2f(m1r - mn1);
    m0r = mn0; m1r = mn1;

    float rs0 = 0.0f, rs1 = 0.0f;
#pragma unroll
    for (int nt = 0; nt < 8; nt++) {
        s[nt][0] = ex2f(s[nt][0] - mn0);
        s[nt][1] = ex2f(s[nt][1] - mn0);
        s[nt][2] = ex2f(s[nt][2] - mn1);
        s[nt][3] = ex2f(s[nt][3] - mn1);
        rs0 += s[nt][0] + s[nt][1];
        rs1 += s[nt][2] + s[nt][3];
    }
    rs0 += __shfl_xor_sync(0xffffffffu, rs0, 1);
    rs0 += __shfl_xor_sync(0xffffffffu, rs0, 2);
    rs1 += __shfl_xor_sync(0xffffffffu, rs1, 1);
    rs1 += __shfl_xor_sync(0xffffffffu, rs1, 2);
    l0r = l0r * a0 + rs0;
    l1r = l1r * a1 + rs1;

#pragma unroll
    for (int i = 0; i < 8; i++) {
        o[i][0] *= a0; o[i][1] *= a0;
        o[i][2] *= a1; o[i][3] *= a1;
    }

    // ---- O += P V ----
#pragma unroll
    for (int ks2 = 0; ks2 < 4; ks2++) {
        uint32_t pa[4];
        pa[0] = pack16(s[2 * ks2][0],     s[2 * ks2][1]);
        pa[1] = pack16(s[2 * ks2][2],     s[2 * ks2][3]);
        pa[2] = pack16(s[2 * ks2 + 1][0], s[2 * ks2 + 1][1]);
        pa[3] = pack16(s[2 * ks2 + 1][2], s[2 * ks2 + 1][3]);

        uint32_t row = ks2 * 16 + lr;
        uint32_t rb = st + AKT + row * 128;
        uint32_t key = row & 7;
#pragma unroll
        for (int dg = 0; dg < 4; dg++) {
            uint32_t ch = dg * 2 + lc;
            uint32_t v0, v1, v2, v3;
            ldm4t(rb + ((ch ^ key) << 4), v0, v1, v2, v3);
            mma_f16(o[2 * dg],     pa, v0, v1);
            mma_f16(o[2 * dg + 1], pa, v2, v3);
        }
    }
}

__global__ __launch_bounds__(128, 3) void attn_f16(
    const __half* __restrict__ q16, const __half* __restrict__ k16,
    const __half* __restrict__ v16, __half* __restrict__ att16)
{
    extern __shared__ __align__(128) char smraw2[];
    const uint32_t sb = cvta_s(smraw2);
    const int qt = gridDim.x - 1 - blockIdx.x;   // heavy tiles first
    const int h = blockIdx.y, b = blockIdx.z;
    const int tid = threadIdx.x, warp = tid >> 5, lane = tid & 31;
    const int q0 = qt * 128;
    const size_t head = (size_t)(b * H_DIM + h) * T_DIM;
    const int nkt = 2 * qt + 2;
    const int lr = lane & 15, lc = lane >> 4;

    // ---- prologue: Q + stage0 ----
    {
        size_t g = (head + q0) * 64;
#pragma unroll
        for (int t = 0; t < 8; t++) {
            int idx = tid + t * 128;
            int r = idx >> 3, c = idx & 7;
            cp16(sb + swz(r, c), q16 + g + (size_t)r * 64 + c * 8);
        }
        kload(k16, v16, head * 64, sb + ASOFF, tid);
        asm volatile("cp.async.commit_group;" ::: "memory");
        asm volatile("cp.async.wait_group 0;" ::: "memory");
    }
    __syncthreads();

    // Q smem row bases for the two m-blocks (Q tile persists in smem)
    const uint32_t qrb0 = sb + (warp * 32 + lr) * 128;
    const uint32_t qkey0 = (warp * 32 + lr) & 7;
    const uint32_t qrb1 = sb + (warp * 32 + 16 + lr) * 128;
    const uint32_t qkey1 = (warp * 32 + 16 + lr) & 7;

    float m[2][2], l[2][2];
#pragma unroll
    for (int mb = 0; mb < 2; mb++) {
        m[mb][0] = -1e30f; m[mb][1] = -1e30f;
        l[mb][0] = 0.0f;   l[mb][1] = 0.0f;
    }
    float o0[8][4], o1[8][4];
#pragma unroll
    for (int i = 0; i < 8; i++)
#pragma unroll
        for (int j = 0; j < 4; j++) { o0[i][j] = 0.0f; o1[i][j] = 0.0f; }

    const int grow = q0 + warp * 32;

    for (int kt = 0; kt < nkt; kt++) {
        if (kt > 0) {
            asm volatile("cp.async.wait_group 0;" ::: "memory");
            __syncthreads();
        }
        if (kt + 1 < nkt) {
            kload(k16, v16, (head + (size_t)(kt + 1) * 64) * 64,
                  sb + ASOFF + ((kt + 1) & 1) * AST, tid);
            asm volatile("cp.async.commit_group;" ::: "memory");
        }
        const uint32_t st = sb + ASOFF + (kt & 1) * AST;
        const bool need_mask = (kt * 64 + 63 > grow);

        mb_tile(st, qrb0, qkey0, lr, lc, lane, kt, grow,
                need_mask, m[0][0], m[0][1], l[0][0], l[0][1], o0);
        mb_tile(st, qrb1, qkey1, lr, lc, lane, kt, grow + 16,
                need_mask, m[1][0], m[1][1], l[1][0], l[1][1], o1);
    }

    // ---- epilogue: normalize, write fp16 att [b,t,C] ----
#pragma unroll
    for (int mb = 0; mb < 2; mb++) {
        float (&o)[8][4] = mb ? o1 : o0;
        const float i0 = 1.0f / l[mb][0], i1 = 1.0f / l[mb][1];
        const int row = q0 + warp * 32 + mb * 16 + (lane >> 2);
        const size_t ob = ((size_t)b * T_DIM + row) * C_DIM + h * 64 + (lane & 3) * 2;
#pragma unroll
        for (int dnt = 0; dnt < 8; dnt++) {
            *(uint32_t*)(att16 + ob + dnt * 8) =
                pack16(o[dnt][0] * i0, o[dnt][1] * i0);
            *(uint32_t*)(att16 + ob + 8 * C_DIM + dnt * 8) =
                pack16(o[dnt][2] * i1, o[dnt][3] * i1);
        }
    }
}

// ---------------------------------------------------------------------------
// launch
// ---------------------------------------------------------------------------
extern "C" void kernel_launch(void* const* d_in, const int* in_sizes, int n_in,
                              void* d_out, int out_size)
{
    const float* x    = (const float*)d_in[0];
    const float* wqkv = (const float*)d_in[1];
    const float* wout = (const float*)d_in[2];
    float* out = (float*)d_out;

    __half *x16, *wq16, *wo16, *att16, *q16, *k16, *v16;
    cudaGetSymbolAddress((void**)&x16, g_x16);
    cudaGetSymbolAddress((void**)&wq16, g_wq16);
    cudaGetSymbolAddress((void**)&wo16, g_wo16);
    cudaGetSymbolAddress((void**)&att16, g_att16);
    cudaGetSymbolAddress((void**)&q16, g_q16);
    cudaGetSymbolAddress((void**)&k16, g_k16);
    cudaGetSymbolAddress((void**)&v16, g_v16);

    const int gemm_smem = GNSTAGE * GSTAGE;     // 98304
    cudaFuncSetAttribute(gemm_f16<0>, cudaFuncAttributeMaxDynamicSharedMemorySize,
                         gemm_smem);
    cudaFuncSetAttribute(gemm_f16<1>, cudaFuncAttributeMaxDynamicSharedMemorySize,
                         gemm_smem);
    const int attn_smem = ASOFF + 2 * AST;      // 49152
    cudaFuncSetAttribute(attn_f16, cudaFuncAttributeMaxDynamicSharedMemorySize,
                         attn_smem);

    // convert all inputs to fp16 in one launch
    {
        const int n0 = MROWS * KDIM / 4;
        const int n1 = 3 * C_DIM * KDIM / 4;
        const int n2 = C_DIM * KDIM / 4;
        const int nt = n0 + n1 + n2;
        cvt_fp16_all<<<(nt + 255) / 256, 256>>>(
            (const float4*)x,    (uint32_t*)x16,  n0,
            (const float4*)wqkv, (uint32_t*)wq16, n1,
            (const float4*)wout, (uint32_t*)wo16, n2);
    }

    // 1) QKV projection, fused epilogue -> q(scaled)/k/v fp16 [b,h,t,d]
    gemm_f16<1><<<dim3(3 * C_DIM / 128, MROWS / 128), 128, gemm_smem>>>(
        x16, wq16, nullptr, q16, k16, v16, 3 * C_DIM, KDIM);

    // 2) flash attention (fp16 tensor-core), writes fp16 att
    attn_f16<<<dim3(T_DIM / 128, H_DIM, B_DIM), 128, attn_smem>>>(
        q16, k16, v16, att16);

    // 3) output projection: [8192, 1024] fp32
    gemm_f16<0><<<dim3(C_DIM / 128, MROWS / 128), 128, gemm_smem>>>(
        att16, wo16, out, nullptr, nullptr, nullptr, C_DIM, KDIM);
}

// round 17
// speedup vs baseline: 1.1213x; 1.1213x over previous
#include <cuda_runtime.h>
#include <cuda_fp16.h>
#include <cstdint>

#define B_DIM 2
#define T_DIM 4096
#define C_DIM 1024
#define H_DIM 16
#define D_DIM 64
#define MROWS (B_DIM * T_DIM)   // 8192
#define KDIM  C_DIM             // 1024

// ---------------- static device scratch (no allocs allowed) ----------------
__device__ __align__(256) __half g_x16[(size_t)MROWS * KDIM];
__device__ __align__(256) __half g_wq16[(size_t)3 * C_DIM * KDIM];
__device__ __align__(256) __half g_wo16[(size_t)C_DIM * KDIM];
__device__ __align__(256) __half g_att16[(size_t)MROWS * C_DIM];
// per-head [b,h,t,d] fp16 (q pre-scaled by 0.125*log2e)
__device__ __align__(256) __half g_q16[(size_t)MROWS * C_DIM];
__device__ __align__(256) __half g_k16[(size_t)MROWS * C_DIM];
__device__ __align__(256) __half g_v16[(size_t)MROWS * C_DIM];

// ---------------------------------------------------------------------------
// PTX helpers
// ---------------------------------------------------------------------------
__device__ __forceinline__ uint32_t cvta_s(const void* p) {
    uint32_t a;
    asm("{ .reg .u64 t; cvta.to.shared.u64 t, %1; cvt.u32.u64 %0, t; }"
        : "=r"(a) : "l"(p));
    return a;
}

__device__ __forceinline__ void cp16(uint32_t dst, const void* src) {
    asm volatile("cp.async.cg.shared.global [%0], [%1], 16;"
                 :: "r"(dst), "l"(src) : "memory");
}

__device__ __forceinline__ void ldm4(uint32_t addr, uint32_t& r0, uint32_t& r1,
                                     uint32_t& r2, uint32_t& r3) {
    asm volatile("ldmatrix.sync.aligned.m8n8.x4.shared.b16 {%0,%1,%2,%3}, [%4];"
                 : "=r"(r0), "=r"(r1), "=r"(r2), "=r"(r3) : "r"(addr));
}

__device__ __forceinline__ void ldm4t(uint32_t addr, uint32_t& r0, uint32_t& r1,
                                      uint32_t& r2, uint32_t& r3) {
    asm volatile("ldmatrix.sync.aligned.m8n8.x4.trans.shared.b16 {%0,%1,%2,%3}, [%4];"
                 : "=r"(r0), "=r"(r1), "=r"(r2), "=r"(r3) : "r"(addr));
}

__device__ __forceinline__ void mma_f16(float* d, const uint32_t* a,
                                        uint32_t b0, uint32_t b1) {
    asm volatile(
        "mma.sync.aligned.m16n8k16.row.col.f32.f16.f16.f32 "
        "{%0,%1,%2,%3}, {%4,%5,%6,%7}, {%8,%9}, {%0,%1,%2,%3};"
        : "+f"(d[0]), "+f"(d[1]), "+f"(d[2]), "+f"(d[3])
        : "r"(a[0]), "r"(a[1]), "r"(a[2]), "r"(a[3]), "r"(b0), "r"(b1));
}

__device__ __forceinline__ float ex2f(float x) {
    float y;
    asm("ex2.approx.f32 %0, %1;" : "=f"(y) : "f"(x));
    return y;
}

__device__ __forceinline__ uint32_t pack16(float lo, float hi) {
    uint32_t r;
    asm("cvt.rn.f16x2.f32 %0, %1, %2;" : "=r"(r) : "f"(hi), "f"(lo));
    return r;
}

// SW128: row r (128B rows), 16B chunk c(0..7) -> byte offset
__device__ __forceinline__ uint32_t swz(uint32_t r, uint32_t c) {
    return r * 128 + ((c ^ (r & 7)) << 4);
}

// ---------------------------------------------------------------------------
// fused convert fp32 -> fp16 for all three inputs in one launch
// ---------------------------------------------------------------------------
__global__ __launch_bounds__(256) void cvt_fp16_all(
    const float4* __restrict__ in0, uint32_t* __restrict__ out0, int n0,
    const float4* __restrict__ in1, uint32_t* __restrict__ out1, int n1,
    const float4* __restrict__ in2, uint32_t* __restrict__ out2, int n2)
{
    int i = blockIdx.x * blockDim.x + threadIdx.x;
    const float4* in;
    uint32_t* out;
    if (i < n0) {
        in = in0; out = out0;
    } else if (i < n0 + n1) {
        i -= n0; in = in1; out = out1;
    } else {
        i -= n0 + n1;
        if (i >= n2) return;
        in = in2; out = out2;
    }
    float4 v = in[i];
    out[2 * i]     = pack16(v.x, v.y);
    out[2 * i + 1] = pack16(v.z, v.w);
}

// ---------------------------------------------------------------------------
// fp16 GEMM (identical to R13 best): CTA 128x128, 4 warps, BK=64, 3-stage.
// MODE 0: write fp32 C.   MODE 1: write fp16 q(scaled)/k/v in [b,h,t,d].
// ---------------------------------------------------------------------------
#define GTILE   16384
#define GSTAGE  32768
#define GNSTAGE 3

__device__ __forceinline__ void g_ldtile(
    const __half* __restrict__ G, int K, int row0, int k0,
    uint32_t base, int tid)
{
#pragma unroll
    for (int t = 0; t < 8; t++) {
        int idx = tid + t * 128;
        int r = idx >> 3, c = idx & 7;
        cp16(base + swz(r, c), G + (size_t)(row0 + r) * K + k0 + c * 8);
    }
}

#define QSCALE 0.180336880f   // 0.125 * log2(e)

template <int MODE>
__global__ __launch_bounds__(128, 2) void gemm_f16(
    const __half* __restrict__ A, const __half* __restrict__ B,
    float* __restrict__ C,
    __half* __restrict__ q16, __half* __restrict__ k16,
    __half* __restrict__ v16, int N, int K)
{
    extern __shared__ __align__(128) char smraw[];
    const uint32_t smbase = cvta_s(smraw);

    const int tid  = threadIdx.x;
    const int wid  = tid >> 5;
    const int lane = tid & 31;
    const int n0 = blockIdx.x * 128;
    const int m0 = blockIdx.y * 128;
    const int wm = (wid & 1) * 64;
    const int wn = (wid >> 1) * 64;
    const int lr = lane & 15;
    const int lc = lane >> 4;

    float acc[4][8][4];
#pragma unroll
    for (int i = 0; i < 4; i++)
#pragma unroll
        for (int j = 0; j < 8; j++)
#pragma unroll
            for (int k = 0; k < 4; k++) acc[i][j][k] = 0.0f;

    const int nch = K / 64;

#pragma unroll
    for (int c = 0; c < 2; c++) {
        uint32_t sb = smbase + c * GSTAGE;
        g_ldtile(A, K, m0, c * 64, sb, tid);
        g_ldtile(B, K, n0, c * 64, sb + GTILE, tid);
        asm volatile("cp.async.commit_group;" ::: "memory");
    }

    for (int c = 0; c < nch; c++) {
        if (c + 1 < nch)
            asm volatile("cp.async.wait_group 1;" ::: "memory");
        else
            asm volatile("cp.async.wait_group 0;" ::: "memory");
        __syncthreads();

        if (c + 2 < nch) {
            uint32_t db = smbase + ((c + 2) % GNSTAGE) * GSTAGE;
            int kk = (c + 2) * 64;
            g_ldtile(A, K, m0, kk, db, tid);
            g_ldtile(B, K, n0, kk, db + GTILE, tid);
            asm volatile("cp.async.commit_group;" ::: "memory");
        }

        uint32_t sb = smbase + (c % GNSTAGE) * GSTAGE;

#pragma unroll
        for (int ks = 0; ks < 4; ks++) {
            const uint32_t ch = ks * 2 + lc;
            uint32_t af[4][4];
#pragma unroll
            for (int mt = 0; mt < 4; mt++) {
                uint32_t row = wm + mt * 16 + lr;
                ldm4(sb + row * 128 + ((ch ^ (row & 7)) << 4),
                     af[mt][0], af[mt][1], af[mt][2], af[mt][3]);
            }
            uint32_t bf[4][4];
#pragma unroll
            for (int p = 0; p < 4; p++) {
                uint32_t row = wn + p * 16 + lr;
                ldm4(sb + GTILE + row * 128 + ((ch ^ (row & 7)) << 4),
                     bf[p][0], bf[p][1], bf[p][2], bf[p][3]);
            }
#pragma unroll
            for (int mt = 0; mt < 4; mt++) {
#pragma unroll
                for (int nt = 0; nt < 8; nt++) {
                    const int p = nt >> 1, h = nt & 1;
                    mma_f16(acc[mt][nt], af[mt], bf[p][h], bf[p][2 + h]);
                }
            }
        }
    }

    const int er = lane >> 2;
    const int ec = (lane & 3) * 2;
#pragma unroll
    for (int mt = 0; mt < 4; mt++) {
#pragma unroll
        for (int nt = 0; nt < 8; nt++) {
            if (MODE == 0) {
                size_t row = (size_t)(m0 + wm + mt * 16 + er);
                int col = n0 + wn + nt * 8 + ec;
                *(float2*)(C + row * N + col) =
                    make_float2(acc[mt][nt][0], acc[mt][nt][1]);
                *(float2*)(C + (row + 8) * N + col) =
                    make_float2(acc[mt][nt][2], acc[mt][nt][3]);
            } else {
                int col = n0 + wn + nt * 8 + ec;
                int type = col >> 10;
                int hh = (col >> 6) & 15;
                int d = col & 63;
                __half* dst = (type == 0) ? q16 : (type == 1) ? k16 : v16;
                float sc = (type == 0) ? QSCALE : 1.0f;
#pragma unroll
                for (int rr = 0; rr < 2; rr++) {
                    int row = m0 + wm + mt * 16 + er + rr * 8;
                    int bb = row >> 12, tt = row & 4095;
                    size_t o = ((size_t)(bb * H_DIM + hh) * T_DIM + tt) * 64 + d;
                    *(uint32_t*)(dst + o) =
                        pack16(acc[mt][nt][2 * rr] * sc,
                               acc[mt][nt][2 * rr + 1] * sc);
                }
            }
        }
    }
}

// ---------------------------------------------------------------------------
// Flash attention, fp16, causal. Br=64 (4 warps x 16 rows), Bc=128:
// HALF the softmax passes / barriers per row vs Bc=64.
// SW128 smem, 2-stage K/V (32KB each), Q 8KB -> 72KB, 2 CTAs/SM.
// q pre-scaled by 0.125*log2e -> scores in log2 units.
// ---------------------------------------------------------------------------
#define AQT2   8192          // Q tile 64x64 fp16
#define AKT2   16384         // K or V tile 128x64 fp16
#define AST2   32768         // stage = K + V
#define ASOFF2 8192

__device__ __forceinline__ void kload2(
    const __half* __restrict__ k16, const __half* __restrict__ v16,
    size_t gbase, uint32_t st, int tid)
{
#pragma unroll
    for (int t = 0; t < 16; t++) {
        int idx = tid + t * 128;            // 0..2047
        int tile = idx >> 10;               // 0=K 1=V
        int rem = idx & 1023;
        int r = rem >> 3, c = rem & 7;      // 128 rows x 8 chunks
        cp16(st + tile * AKT2 + swz(r, c),
             (tile ? v16 : k16) + gbase + (size_t)r * 64 + c * 8);
    }
}

__global__ __launch_bounds__(128, 2) void attn_f16(
    const __half* __restrict__ q16, const __half* __restrict__ k16,
    const __half* __restrict__ v16, __half* __restrict__ att16)
{
    extern __shared__ __align__(128) char smraw2[];
    const uint32_t sb = cvta_s(smraw2);
    const int qt = gridDim.x - 1 - blockIdx.x;   // heavy tiles first
    const int h = blockIdx.y, b = blockIdx.z;
    const int tid = threadIdx.x, warp = tid >> 5, lane = tid & 31;
    const int q0 = qt * 64;
    const size_t head = (size_t)(b * H_DIM + h) * T_DIM;
    const int nkt = qt / 2 + 1;                  // 128-wide k tiles
    const int lr = lane & 15, lc = lane >> 4;

    // ---- prologue: Q (64x64) + stage0 ----
    {
        size_t g = (head + q0) * 64;
#pragma unroll
        for (int t = 0; t < 4; t++) {
            int idx = tid + t * 128;        // 0..511
            int r = idx >> 3, c = idx & 7;
            cp16(sb + swz(r, c), q16 + g + (size_t)r * 64 + c * 8);
        }
        kload2(k16, v16, head * 64, sb + ASOFF2, tid);
        asm volatile("cp.async.commit_group;" ::: "memory");
        asm volatile("cp.async.wait_group 0;" ::: "memory");
    }
    __syncthreads();

    // ---- Q fragments, resident (16 rows x 4 ks) ----
    uint32_t qf[4][4];
    {
        uint32_t row = warp * 16 + lr;
        uint32_t rb = sb + row * 128;
        uint32_t key = row & 7;
#pragma unroll
        for (int ks = 0; ks < 4; ks++) {
            uint32_t ch = ks * 2 + lc;
            ldm4(rb + ((ch ^ key) << 4),
                 qf[ks][0], qf[ks][1], qf[ks][2], qf[ks][3]);
        }
    }

    float m0 = -1e30f, m1 = -1e30f, l0 = 0.0f, l1 = 0.0f;
    float o[8][4];
#pragma unroll
    for (int i = 0; i < 8; i++)
#pragma unroll
        for (int j = 0; j < 4; j++) o[i][j] = 0.0f;

    const int grow = q0 + warp * 16;

    for (int kt = 0; kt < nkt; kt++) {
        if (kt > 0) {
            asm volatile("cp.async.wait_group 0;" ::: "memory");
            __syncthreads();
        }
        if (kt + 1 < nkt) {
            kload2(k16, v16, (head + (size_t)(kt + 1) * 128) * 64,
                   sb + ASOFF2 + ((kt + 1) & 1) * AST2, tid);
            asm volatile("cp.async.commit_group;" ::: "memory");
        }
        const uint32_t st = sb + ASOFF2 + (kt & 1) * AST2;

        // ---- S = Q K^T (16 rows x 128 cols) ----
        float s[16][4];
#pragma unroll
        for (int i = 0; i < 16; i++)
#pragma unroll
            for (int j = 0; j < 4; j++) s[i][j] = 0.0f;

#pragma unroll
        for (int ks = 0; ks < 4; ks++) {
            uint32_t ch = ks * 2 + lc;
#pragma unroll
            for (int ng = 0; ng < 8; ng++) {
                uint32_t row = ng * 16 + lr;
                uint32_t h0, h1, h2, h3;
                ldm4(st + row * 128 + ((ch ^ (row & 7)) << 4), h0, h1, h2, h3);
                mma_f16(s[2 * ng],     qf[ks], h0, h2);
                mma_f16(s[2 * ng + 1], qf[ks], h1, h3);
            }
        }

        // ---- causal mask ----
        if (kt * 128 + 127 > grow) {
            const int rb0 = grow + (lane >> 2);
            const int cb = kt * 128 + (lane & 3) * 2;
#pragma unroll
            for (int nt = 0; nt < 16; nt++) {
                int c0 = cb + nt * 8;
                if (c0     > rb0)     s[nt][0] = -1e30f;
                if (c0 + 1 > rb0)     s[nt][1] = -1e30f;
                if (c0     > rb0 + 8) s[nt][2] = -1e30f;
                if (c0 + 1 > rb0 + 8) s[nt][3] = -1e30f;
            }
        }

        // ---- online softmax (one pass per 128 cols) ----
        float mx0 = s[0][0], mx1 = s[0][2];
#pragma unroll
        for (int nt = 0; nt < 16; nt++) {
            mx0 = fmaxf(mx0, fmaxf(s[nt][0], s[nt][1]));
            mx1 = fmaxf(mx1, fmaxf(s[nt][2], s[nt][3]));
        }
        mx0 = fmaxf(mx0, __shfl_xor_sync(0xffffffffu, mx0, 1));
        mx0 = fmaxf(mx0, __shfl_xor_sync(0xffffffffu, mx0, 2));
        mx1 = fmaxf(mx1, __shfl_xor_sync(0xffffffffu, mx1, 1));
        mx1 = fmaxf(mx1, __shfl_xor_sync(0xffffffffu, mx1, 2));

        float mn0 = fmaxf(m0, mx0), mn1 = fmaxf(m1, mx1);
        float a0 = ex2f(m0 - mn0);
        float a1 = ex2f(m1 - mn1);
        m0 = mn0; m1 = mn1;

        float rs0 = 0.0f, rs1 = 0.0f;
#pragma unroll
        for (int nt = 0; nt < 16; nt++) {
            s[nt][0] = ex2f(s[nt][0] - mn0);
            s[nt][1] = ex2f(s[nt][1] - mn0);
            s[nt][2] = ex2f(s[nt][2] - mn1);
            s[nt][3] = ex2f(s[nt][3] - mn1);
            rs0 += s[nt][0] + s[nt][1];
            rs1 += s[nt][2] + s[nt][3];
        }
        rs0 += __shfl_xor_sync(0xffffffffu, rs0, 1);
        rs0 += __shfl_xor_sync(0xffffffffu, rs0, 2);
        rs1 += __shfl_xor_sync(0xffffffffu, rs1, 1);
        rs1 += __shfl_xor_sync(0xffffffffu, rs1, 2);
        l0 = l0 * a0 + rs0;
        l1 = l1 * a1 + rs1;

#pragma unroll
        for (int i = 0; i < 8; i++) {
            o[i][0] *= a0; o[i][1] *= a0;
            o[i][2] *= a1; o[i][3] *= a1;
        }

        // ---- O += P V (K=128 -> 8 ksteps) ----
#pragma unroll
        for (int ks2 = 0; ks2 < 8; ks2++) {
            uint32_t pa[4];
            pa[0] = pack16(s[2 * ks2][0],     s[2 * ks2][1]);
            pa[1] = pack16(s[2 * ks2][2],     s[2 * ks2][3]);
            pa[2] = pack16(s[2 * ks2 + 1][0], s[2 * ks2 + 1][1]);
            pa[3] = pack16(s[2 * ks2 + 1][2], s[2 * ks2 + 1][3]);

            uint32_t row = ks2 * 16 + lr;
            uint32_t rb = st + AKT2 + row * 128;
            uint32_t key = row & 7;
#pragma unroll
            for (int dg = 0; dg < 4; dg++) {
                uint32_t ch = dg * 2 + lc;
                uint32_t v0, v1, v2, v3;
                ldm4t(rb + ((ch ^ key) << 4), v0, v1, v2, v3);
                mma_f16(o[2 * dg],     pa, v0, v1);
                mma_f16(o[2 * dg + 1], pa, v2, v3);
            }
        }
    }

    // ---- epilogue: normalize, write fp16 att [b,t,C] ----
    const float i0 = 1.0f / l0, i1 = 1.0f / l1;
    const int row = q0 + warp * 16 + (lane >> 2);
    const size_t ob = ((size_t)b * T_DIM + row) * C_DIM + h * 64 + (lane & 3) * 2;
#pragma unroll
    for (int dnt = 0; dnt < 8; dnt++) {
        *(uint32_t*)(att16 + ob + dnt * 8) =
            pack16(o[dnt][0] * i0, o[dnt][1] * i0);
        *(uint32_t*)(att16 + ob + 8 * C_DIM + dnt * 8) =
            pack16(o[dnt][2] * i1, o[dnt][3] * i1);
    }
}

// ---------------------------------------------------------------------------
// launch
// ---------------------------------------------------------------------------
extern "C" void kernel_launch(void* const* d_in, const int* in_sizes, int n_in,
                              void* d_out, int out_size)
{
    const float* x    = (const float*)d_in[0];
    const float* wqkv = (const float*)d_in[1];
    const float* wout = (const float*)d_in[2];
    float* out = (float*)d_out;

    __half *x16, *wq16, *wo16, *att16, *q16, *k16, *v16;
    cudaGetSymbolAddress((void**)&x16, g_x16);
    cudaGetSymbolAddress((void**)&wq16, g_wq16);
    cudaGetSymbolAddress((void**)&wo16, g_wo16);
    cudaGetSymbolAddress((void**)&att16, g_att16);
    cudaGetSymbolAddress((void**)&q16, g_q16);
    cudaGetSymbolAddress((void**)&k16, g_k16);
    cudaGetSymbolAddress((void**)&v16, g_v16);

    const int gemm_smem = GNSTAGE * GSTAGE;     // 98304
    cudaFuncSetAttribute(gemm_f16<0>, cudaFuncAttributeMaxDynamicSharedMemorySize,
                         gemm_smem);
    cudaFuncSetAttribute(gemm_f16<1>, cudaFuncAttributeMaxDynamicSharedMemorySize,
                         gemm_smem);
    const int attn_smem = ASOFF2 + 2 * AST2;    // 73728
    cudaFuncSetAttribute(attn_f16, cudaFuncAttributeMaxDynamicSharedMemorySize,
                         attn_smem);

    // convert all inputs to fp16 in one launch
    {
        const int n0 = MROWS * KDIM / 4;
        const int n1 = 3 * C_DIM * KDIM / 4;
        const int n2 = C_DIM * KDIM / 4;
        const int nt = n0 + n1 + n2;
        cvt_fp16_all<<<(nt + 255) / 256, 256>>>(
            (const float4*)x,    (uint32_t*)x16,  n0,
            (const float4*)wqkv, (uint32_t*)wq16, n1,
            (const float4*)wout, (uint32_t*)wo16, n2);
    }

    // 1) QKV projection, fused epilogue -> q(scaled)/k/v fp16 [b,h,t,d]
    gemm_f16<1><<<dim3(3 * C_DIM / 128, MROWS / 128), 128, gemm_smem>>>(
        x16, wq16, nullptr, q16, k16, v16, 3 * C_DIM, KDIM);

    // 2) flash attention (fp16 tensor-core), Br=64 / Bc=128
    attn_f16<<<dim3(T_DIM / 64, H_DIM, B_DIM), 128, attn_smem>>>(
        q16, k16, v16, att16);

    // 3) output projection: [8192, 1024] fp32
    gemm_f16<0><<<dim3(C_DIM / 128, MROWS / 128), 128, gemm_smem>>>(
        att16, wo16, out, nullptr, nullptr, nullptr, C_DIM, KDIM);
}